// round 5
// baseline (speedup 1.0000x reference)
#include <cuda_runtime.h>
#include <cuda_bf16.h>
#include <cstdint>

#define S 4096
#define GRID 128
#define BLOCK 512
#define NWARP 16
#define RPB 32             // rows per block
#define RPG 8              // rows per warp row-group
#define KQ 1024            // K-window per warp (quarter of S)
#define ROWSTRIDE (S / 8)  // uint4 per row

// ---------------- device-global scratch ----------------
static __device__ __nv_bfloat16 g_M[(size_t)S * S];     // exp(log_trans), bf16
static __device__ float g_w[2][S];                      // ping-pong unnormalized filter
static __device__ unsigned long long g_flag[2][GRID];   // ping-pong {f32 partialZ:hi, u32 gen:lo}

// ---------------- prep: M = bf16(exp(log_trans)); reset flags ----------------
__global__ void hmm_prep_kernel(const float* __restrict__ log_trans) {
    size_t gtid = (size_t)blockIdx.x * blockDim.x + threadIdx.x;
    if (gtid < 2 * GRID) g_flag[gtid / GRID][gtid % GRID] = 0ull;
    const size_t n4 = (size_t)S * S / 4;
    const size_t stride = (size_t)gridDim.x * blockDim.x;
    for (size_t i = gtid; i < n4; i += stride) {
        float4 v = reinterpret_cast<const float4*>(log_trans)[i];
        __nv_bfloat162 lo, hi;
        lo.x = __float2bfloat16(__expf(v.x));
        lo.y = __float2bfloat16(__expf(v.y));
        hi.x = __float2bfloat16(__expf(v.z));
        hi.y = __float2bfloat16(__expf(v.w));
        reinterpret_cast<__nv_bfloat162*>(g_M)[2 * i]     = lo;
        reinterpret_cast<__nv_bfloat162*>(g_M)[2 * i + 1] = hi;
    }
}

// ---------------- helpers ----------------
__device__ __forceinline__ float warp_sum(float v) {
#pragma unroll
    for (int o = 16; o; o >>= 1) v += __shfl_xor_sync(0xffffffffu, v, o);
    return v;
}

__device__ __forceinline__ unsigned long long cvt2(unsigned u) {   // bf16x2 -> f32x2, exact
    unsigned lo = u << 16;
    unsigned hi = u & 0xffff0000u;
    unsigned long long r;
    asm("mov.b64 %0, {%1, %2};" : "=l"(r) : "r"(lo), "r"(hi));
    return r;
}

__device__ __forceinline__ unsigned long long fma2(unsigned long long a,
                                                   unsigned long long b,
                                                   unsigned long long c) {
    unsigned long long d;
    asm("fma.rn.f32x2 %0, %1, %2, %3;" : "=l"(d) : "l"(a), "l"(b), "l"(c));
    return d;
}

__device__ __forceinline__ float f32x2_hsum(unsigned long long v) {
    unsigned lo, hi;
    asm("mov.b64 {%0, %1}, %2;" : "=r"(lo), "=r"(hi) : "l"(v));
    return __uint_as_float(lo) + __uint_as_float(hi);
}

__device__ __forceinline__ unsigned long long ldacq(const unsigned long long* p) {
    unsigned long long v;
    asm volatile("ld.acquire.gpu.global.b64 %0, [%1];" : "=l"(v) : "l"(p) : "memory");
    return v;
}
__device__ __forceinline__ void strel(unsigned long long* p, unsigned long long v) {
    asm volatile("st.release.gpu.global.b64 [%0], %1;" :: "l"(p), "l"(v) : "memory");
}
__device__ __forceinline__ void strelax(float* p, float v) {
    asm volatile("st.relaxed.gpu.global.f32 [%0], %1;" :: "l"(p), "f"(v) : "memory");
}

// Quarter poll: one flag per lane. Exact-match spin is safe: slot(gen) is
// rewritten only at gen+2, and every block consumes all 4 quarters (= all
// 128 producers), so gen+2 publish implies every block finished gen.
// Returns quarter partial of Z (flag payloads).
__device__ __forceinline__ float poll_quarter(unsigned gen, int q, int lane) {
    const unsigned long long* p = g_flag[gen & 1] + q * 32 + lane;
    unsigned long long x;
    do { x = ldacq(p); } while (__any_sync(0xffffffffu, (unsigned)x != gen));
    return warp_sum(__uint_as_float((unsigned)(x >> 32)));
}

// Full poll (final Z_T only)
__device__ __forceinline__ float poll_all(unsigned gen, int lane) {
    const unsigned long long* base = g_flag[gen & 1];
    unsigned long long x0, x1, x2, x3;
    for (;;) {
        x0 = ldacq(base + lane);
        x1 = ldacq(base + lane + 32);
        x2 = ldacq(base + lane + 64);
        x3 = ldacq(base + lane + 96);
        if (((unsigned)x0 == gen) & ((unsigned)x1 == gen) &
            ((unsigned)x2 == gen) & ((unsigned)x3 == gen)) break;
    }
    float z = __uint_as_float((unsigned)(x0 >> 32)) +
              __uint_as_float((unsigned)(x1 >> 32)) +
              __uint_as_float((unsigned)(x2 >> 32)) +
              __uint_as_float((unsigned)(x3 >> 32));
    return warp_sum(z);
}

// dot products: 8 rows x 1024-wide K window against smem w
template <bool CACHED>
__device__ __forceinline__ void dot8(const uint4* __restrict__ A,
                                     const float* __restrict__ swq,
                                     int lane, unsigned long long* acc) {
#pragma unroll
    for (int c = 0; c < 4; ++c) {
        const int kb = c * 32 + lane;
        const ulonglong2 w01 = *reinterpret_cast<const ulonglong2*>(swq + c * 256 + lane * 8);
        const ulonglong2 w23 = *reinterpret_cast<const ulonglong2*>(swq + c * 256 + lane * 8 + 4);
#pragma unroll
        for (int r = 0; r < 8; ++r) {
            uint4 a;
            if (CACHED) {
                a = A[r * ROWSTRIDE + kb];
            } else {
                float4 t = __ldcg(reinterpret_cast<const float4*>(A) + r * ROWSTRIDE + kb);
                a = *reinterpret_cast<uint4*>(&t);
            }
            acc[r] = fma2(cvt2(a.x), w01.x, acc[r]);
            acc[r] = fma2(cvt2(a.y), w01.y, acc[r]);
            acc[r] = fma2(cvt2(a.z), w23.x, acc[r]);
            acc[r] = fma2(cvt2(a.w), w23.y, acc[r]);
        }
    }
}

// ---------------- persistent forward-filter kernel ----------------
__global__ void __launch_bounds__(BLOCK, 1) hmm_main_kernel(
    const float* __restrict__ log_M0,
    const float* __restrict__ log_emit,
    const int*   __restrict__ Tptr,
    float*       __restrict__ out)
{
    __shared__ float sw[S];                            // current w (linear space)
    __shared__ __align__(16) float s_red[2][RPB][4];   // double-buffered partials
    __shared__ float s_zq[2][4];                       // double-buffered quarter Z sums

    const int tid  = threadIdx.x;
    const int lane = tid & 31;
    const int warp = tid >> 5;
    const int g    = warp >> 2;   // row group 0..3
    const int q    = warp & 3;    // K quarter 0..3
    const int bid  = blockIdx.x;
    const int T    = *Tptr;

    const int r0 = bid * RPB;
    const uint4* A = reinterpret_cast<const uint4*>(
        g_M + (size_t)(r0 + g * RPG) * S + q * KQ);
    const float* swq = sw + q * KQ;

    double lik = 0.0;

    // ---- t = 0: w0 = exp(log_M0 + log_emit[0]) ----
    if (warp == 0) {
        int row = r0 + lane;
        float v = __expf(__ldcg(log_M0 + row) + __ldcg(log_emit + row));
        strelax(&g_w[0][row], v);
        float part = warp_sum(v);
        __syncwarp();
        if (lane == 0)
            strel(&g_flag[1][bid],
                  ((unsigned long long)__float_as_uint(part) << 32) | 1u);
    }
    // no block sync needed: consumers self-synchronize on global flags

    for (int t = 1; t <= T; ++t) {
        const int slot = t & 1;                 // input flag slot / prev w buffer
        const int prev = (t - 1) & 1;
        const int cur  = t & 1;
        const unsigned gen_out = (unsigned)(t + 1);

        // emit prefetch (warp 0 only; overlaps poll/copy)
        float em = 0.f;
        if (warp == 0) em = __ldcg(log_emit + (size_t)t * S + r0 + lane);

        // quarter producers (g==0 warps): poll 32 flags, stage quarter into smem
        if (g == 0) {
            float zq = poll_quarter((unsigned)t, q, lane);
            if (lane == 0) s_zq[slot][q] = zq;
            const float4* src = reinterpret_cast<const float4*>(g_w[prev] + q * KQ);
            float4*       dst = reinterpret_cast<float4*>(sw + q * KQ);
#pragma unroll
            for (int j = 0; j < 8; ++j)
                dst[j * 32 + lane] = __ldcg(src + j * 32 + lane);
        }
        // per-quarter handoff (ids 1..4, 4 warps = 128 threads each)
        asm volatile("bar.sync %0, %1;" :: "r"(q + 1), "r"(128) : "memory");

        unsigned long long acc[8] = {0ull, 0ull, 0ull, 0ull, 0ull, 0ull, 0ull, 0ull};
        if (g < 3) dot8<true >(A, swq, lane, acc);
        else       dot8<false>(A, swq, lane, acc);

#pragma unroll
        for (int r = 0; r < 8; ++r) {
            float s = warp_sum(f32x2_hsum(acc[r]));
            if (lane == 0) s_red[slot][g * RPG + r][q] = s;
        }
        __syncthreads();   // the single block-wide sync per step

        // epilogue: warp 0 combines, normalizes with Z_{t-1}, publishes
        if (warp == 0) {
            float4 p = *reinterpret_cast<const float4*>(s_red[slot][lane]);
            float dotv = (p.x + p.y) + (p.z + p.w);
            float Z = (s_zq[slot][0] + s_zq[slot][1]) + (s_zq[slot][2] + s_zq[slot][3]);
            float invZ = 1.0f / Z;
            if (bid == 0 && lane == 0) lik += (double)logf(Z);
            float v = dotv * __expf(em) * invZ;
            strelax(&g_w[cur][r0 + lane], v);
            float part = warp_sum(v);
            __syncwarp();
            if (lane == 0)
                strel(&g_flag[gen_out & 1][bid],
                      ((unsigned long long)__float_as_uint(part) << 32) | gen_out);
        }
        // no trailing sync: s_red/s_zq double-buffered; racers into t+1 are
        // gated by global flags which require epilogues elsewhere, and slot
        // reuse at t+2 is ordered behind syncthreads(t+1).
    }

    // final Z_T
    if (bid == 0 && warp == 0) {
        float Z = poll_all((unsigned)(T + 1), lane);
        if (lane == 0) {
            lik += (double)logf(Z);
            out[0] = (float)lik;
        }
    }
}

// ---------------- launch ----------------
extern "C" void kernel_launch(void* const* d_in, const int* in_sizes, int n_in,
                              void* d_out, int out_size) {
    const float* log_M0    = (const float*)d_in[0];
    const float* log_trans = (const float*)d_in[1];
    const float* log_emit  = (const float*)d_in[2];
    const int*   Tptr      = (const int*)d_in[3];
    float* out = (float*)d_out;

    hmm_prep_kernel<<<2048, 256>>>(log_trans);
    hmm_main_kernel<<<GRID, BLOCK>>>(log_M0, log_emit, Tptr, out);
}